// round 4
// baseline (speedup 1.0000x reference)
#include <cuda_runtime.h>
#include <cuda_bf16.h>
#include <math.h>

#define N_GAUSS 2048
#define HEIGHT  192
#define WIDTH   192
#define HW      (HEIGHT*WIDTH)
#define ALPHA_MAX 0.999f
#define ALPHA_MIN (1.0f/255.0f)

// Depth-sorted gaussian data (total 80 KB -> fully L1/L2 resident)
__device__ float4 g_A[N_GAUSS];  // mx, my, conic_a, conic_b
__device__ float4 g_B[N_GAUSS];  // conic_c, opacity, col_r, col_g
__device__ float2 g_C[N_GAUSS];  // col_b, sigma_threshold = log(255*op)+margin
__device__ float4 g_D[N_GAUSS];  // mx, my, rx, ry : cull record (one LDG.128)

// ---------------------------------------------------------------------------
// Kernel 1: rank-by-counting sort (keys unique) fused with param scatter.
// 128 blocks x 256 threads. Block handles 16 gaussians; 16 slice-threads per
// gaussian each count 128 keys; ranks summed; 16 threads scatter params.
// ---------------------------------------------------------------------------
__global__ void __launch_bounds__(256)
sort_scatter_kernel(const float* __restrict__ means2d,
                    const float* __restrict__ conics,
                    const float* __restrict__ colors,
                    const float* __restrict__ opacities,
                    const float* __restrict__ depths)
{
    __shared__ unsigned long long keys[N_GAUSS];
    __shared__ int cnt[16][17];          // padded vs bank conflicts
    const int tid = threadIdx.x;

    // (depth_bits << 32) | index : depths > 0 so float bits order like floats;
    // index makes keys unique.
    #pragma unroll
    for (int i = tid; i < N_GAUSS; i += 256)
        keys[i] = (((unsigned long long)__float_as_uint(depths[i])) << 32) | (unsigned)i;
    __syncthreads();

    const int gl    = tid & 15;          // gaussian-within-block
    const int slice = tid >> 4;          // 0..15
    const unsigned long long mykey = keys[blockIdx.x * 16 + gl];

    int c = 0;
    const int s0 = slice * (N_GAUSS / 16);
    #pragma unroll 8
    for (int i = 0; i < N_GAUSS / 16; ++i)
        c += (keys[s0 + i] < mykey);
    cnt[slice][gl] = c;
    __syncthreads();

    if (tid < 16) {
        int rank = 0;
        #pragma unroll
        for (int s = 0; s < 16; ++s) rank += cnt[s][tid];
        int src = blockIdx.x * 16 + tid;
        float mx = means2d[2*src + 0];
        float my = means2d[2*src + 1];
        float ca = conics[3*src + 0];
        float cb = conics[3*src + 1];
        float cc = conics[3*src + 2];
        float op = opacities[src];
        float cr = colors[3*src + 0];
        float cg = colors[3*src + 1];
        float cbl= colors[3*src + 2];
        // alpha >= 1/255  <=>  sigma <= log(255*op); +margin so the cheap
        // reject never drops a gaussian the exact in-branch check keeps.
        float t = logf(255.0f * op) + 1e-4f;
        // Support ellipse sigma<=t AABB half-extents:
        //   rx = sqrt(2t*cc/det), ry = sqrt(2t*ca/det)
        float det = ca * cc - cb * cb;
        float inv = 2.0f * fmaxf(t, 0.0f) / det;
        float rx = sqrtf(fmaxf(inv * cc, 0.0f)) + 1e-3f;
        float ry = sqrtf(fmaxf(inv * ca, 0.0f)) + 1e-3f;
        g_A[rank] = make_float4(mx, my, ca, cb);
        g_B[rank] = make_float4(cc, op, cr, cg);
        g_C[rank] = make_float2(cbl, t);
        g_D[rank] = make_float4(mx, my, rx, ry);
    }
}

// ---------------------------------------------------------------------------
// Kernel 2: per-warp strip-culled front-to-back compositing.
// 8x8 pixel tile per block (64 threads, 2 warps); each warp owns an 8x4 strip.
// 576 blocks -> ~4 co-resident per SM + dynamic load balancing. No smem:
// the 80KB dataset is L1-resident; cull is one coalesced LDG.128 per lane,
// survivor reads are warp-uniform broadcasts. Zero block barriers.
// ---------------------------------------------------------------------------
__global__ void __launch_bounds__(64)
render_kernel(const float* __restrict__ background, float* __restrict__ out)
{
    const int tid  = threadIdx.x;
    const int warp = tid >> 5, lane = tid & 31;
    const int x = blockIdx.x * 8 + (tid & 7);
    const int y = blockIdx.y * 8 + ((tid >> 3) & 3) + 4 * warp;
    const float px = (float)x + 0.5f;
    const float py = (float)y + 0.5f;

    // This warp's 8x4 pixel-center strip bounds.
    const float sxmin = blockIdx.x * 8 + 0.5f;
    const float sxmax = sxmin + 7.0f;
    const float symin = blockIdx.y * 8 + 4 * warp + 0.5f;
    const float symax = symin + 3.0f;

    float T = 1.0f;
    float accr = 0.0f, accg = 0.0f, accb = 0.0f;

    for (int g = 0; g < N_GAUSS; g += 32) {
        // Lane-parallel cull of this 32-group against the strip (one LDG.128).
        float4 d = g_D[g + lane];
        bool pred = (d.x - d.z <= sxmax) & (d.x + d.z >= sxmin) &
                    (d.y - d.w <= symax) & (d.y + d.w >= symin);
        unsigned mask = __ballot_sync(0xffffffffu, pred);

        // Uniform in-order walk over survivors (broadcast loads).
        while (mask) {
            int j = g + (__ffs(mask) - 1);
            mask &= mask - 1;
            float4 A = g_A[j];
            float dx = px - A.x;
            float dy = py - A.y;
            float4 B = g_B[j];
            float2 C = g_C[j];
            float sigma = 0.5f * (A.z * dx * dx + B.x * dy * dy) + A.w * dx * dy;
            if (sigma > 0.0f && sigma < C.y) {
                float alpha = fminf(ALPHA_MAX, B.y * __expf(-sigma));
                if (alpha >= ALPHA_MIN) {   // exact reference condition
                    float w = T * alpha;
                    accr = fmaf(w, B.z, accr);
                    accg = fmaf(w, B.w, accg);
                    accb = fmaf(w, C.x, accb);
                    T *= (1.0f - alpha);
                }
            }
        }
        // Per-warp early exit: remaining contributions bounded by T.
        if (!__ballot_sync(0xffffffffu, T >= 1e-7f)) break;
    }

    const int pix = y * WIDTH + x;
    out[0 * HW + pix] = fmaf(background[0], T, accr);
    out[1 * HW + pix] = fmaf(background[1], T, accg);
    out[2 * HW + pix] = fmaf(background[2], T, accb);
}

// ---------------------------------------------------------------------------
extern "C" void kernel_launch(void* const* d_in, const int* in_sizes, int n_in,
                              void* d_out, int out_size)
{
    const float* means2d    = (const float*)d_in[0];
    const float* conics     = (const float*)d_in[1];
    const float* colors     = (const float*)d_in[2];
    const float* opacities  = (const float*)d_in[3];
    const float* depths     = (const float*)d_in[4];
    const float* background = (const float*)d_in[5];
    float* out = (float*)d_out;

    sort_scatter_kernel<<<128, 256>>>(means2d, conics, colors, opacities, depths);
    dim3 grid(WIDTH / 8, HEIGHT / 8);
    render_kernel<<<grid, 64>>>(background, out);
}

// round 5
// speedup vs baseline: 1.2554x; 1.2554x over previous
#include <cuda_runtime.h>
#include <cuda_bf16.h>
#include <math.h>

#define N_GAUSS 2048
#define HEIGHT  192
#define WIDTH   192
#define HW      (HEIGHT*WIDTH)
#define ALPHA_MAX 0.999f
#define ALPHA_MIN (1.0f/255.0f)
#define CHUNK   1024

// Depth-sorted gaussian data
__device__ float4 g_A[N_GAUSS];  // mx, my, conic_a, conic_b
__device__ float4 g_B[N_GAUSS];  // conic_c, opacity, col_r, col_g
__device__ float2 g_C[N_GAUSS];  // col_b, sigma_threshold = log(255*op)+margin
__device__ float2 g_D[N_GAUSS];  // rx, ry : conservative AABB half-extents

// ---------------------------------------------------------------------------
// Kernel 1: rank-by-counting sort (keys unique) fused with param scatter.
// ---------------------------------------------------------------------------
__global__ void __launch_bounds__(256)
sort_scatter_kernel(const float* __restrict__ means2d,
                    const float* __restrict__ conics,
                    const float* __restrict__ colors,
                    const float* __restrict__ opacities,
                    const float* __restrict__ depths)
{
    __shared__ unsigned long long keys[N_GAUSS];
    __shared__ int cnt[16][17];
    const int tid = threadIdx.x;

    #pragma unroll
    for (int i = tid; i < N_GAUSS; i += 256)
        keys[i] = (((unsigned long long)__float_as_uint(depths[i])) << 32) | (unsigned)i;
    __syncthreads();

    const int gl    = tid & 15;
    const int slice = tid >> 4;
    const unsigned long long mykey = keys[blockIdx.x * 16 + gl];

    int c = 0;
    const int s0 = slice * (N_GAUSS / 16);
    #pragma unroll 8
    for (int i = 0; i < N_GAUSS / 16; ++i)
        c += (keys[s0 + i] < mykey);
    cnt[slice][gl] = c;
    __syncthreads();

    if (tid < 16) {
        int rank = 0;
        #pragma unroll
        for (int s = 0; s < 16; ++s) rank += cnt[s][tid];
        int src = blockIdx.x * 16 + tid;
        float mx = means2d[2*src + 0];
        float my = means2d[2*src + 1];
        float ca = conics[3*src + 0];
        float cb = conics[3*src + 1];
        float cc = conics[3*src + 2];
        float op = opacities[src];
        float cr = colors[3*src + 0];
        float cg = colors[3*src + 1];
        float cbl= colors[3*src + 2];
        float t = logf(255.0f * op) + 1e-4f;           // alpha>=1/255 bound
        float det = ca * cc - cb * cb;
        float inv = 2.0f * fmaxf(t, 0.0f) / det;
        float rx = sqrtf(fmaxf(inv * cc, 0.0f)) + 1e-3f;
        float ry = sqrtf(fmaxf(inv * ca, 0.0f)) + 1e-3f;
        g_A[rank] = make_float4(mx, my, ca, cb);
        g_B[rank] = make_float4(cc, op, cr, cg);
        g_C[rank] = make_float2(cbl, t);
        g_D[rank] = make_float2(rx, ry);
    }
}

// ---------------------------------------------------------------------------
// Kernel 2: per-warp strip-culled compositing, 2-wide survivor walk.
// 16x16 tile per block (256 threads); each warp owns a 16x2 strip.
// Gaussians staged in two 1024-chunks (48KB smem). Survivors are processed
// in pairs: loads + sigma + exp for the pair are independent (ILP), the
// T-composite chain stays exactly ordered.
// ---------------------------------------------------------------------------
__global__ void __launch_bounds__(256)
render_kernel(const float* __restrict__ background, float* __restrict__ out)
{
    __shared__ float4 sA[CHUNK];
    __shared__ float4 sB[CHUNK];
    __shared__ float2 sC[CHUNK];
    __shared__ float2 sD[CHUNK];

    const int tid  = threadIdx.x;
    const int warp = tid >> 5, lane = tid & 31;
    const int x = blockIdx.x * 16 + (tid & 15);
    const int y = blockIdx.y * 16 + (tid >> 4);
    const float px = (float)x + 0.5f;
    const float py = (float)y + 0.5f;

    const float sxmin = blockIdx.x * 16 + 0.5f;
    const float sxmax = blockIdx.x * 16 + 15.5f;
    const float symin = blockIdx.y * 16 + 2 * warp + 0.5f;
    const float symax = symin + 1.0f;

    float T = 1.0f;
    float accr = 0.0f, accg = 0.0f, accb = 0.0f;
    bool wdone = false;

    for (int base = 0; base < N_GAUSS; base += CHUNK) {
        if (base) __syncthreads();
        #pragma unroll
        for (int k = 0; k < CHUNK / 256; ++k) {
            int i = tid + k * 256;
            sA[i] = g_A[base + i];
            sB[i] = g_B[base + i];
            sC[i] = g_C[base + i];
            sD[i] = g_D[base + i];
        }
        __syncthreads();

        if (!wdone) {
            for (int g = 0; g < CHUNK; g += 32) {
                float4 a = sA[g + lane];
                float2 r = sD[g + lane];
                bool pred = (a.x - r.x <= sxmax) & (a.x + r.x >= sxmin) &
                            (a.y - r.y <= symax) & (a.y + r.y >= symin);
                unsigned mask = __ballot_sync(0xffffffffu, pred);

                // 2-wide in-order walk over survivors.
                while (mask) {
                    int j0 = g + (__ffs(mask) - 1);
                    mask &= mask - 1;
                    bool two = (mask != 0);
                    int j1 = two ? (g + (__ffs(mask) - 1)) : j0;
                    if (two) mask &= mask - 1;

                    // Unconditional paired loads (j1 aliases j0 when single)
                    float4 A0 = sA[j0], A1 = sA[j1];
                    float4 B0 = sB[j0], B1 = sB[j1];
                    float2 C0 = sC[j0], C1 = sC[j1];

                    float dx0 = px - A0.x, dy0 = py - A0.y;
                    float dx1 = px - A1.x, dy1 = py - A1.y;
                    float sg0 = 0.5f * (A0.z*dx0*dx0 + B0.x*dy0*dy0) + A0.w*dx0*dy0;
                    float sg1 = 0.5f * (A1.z*dx1*dx1 + B1.x*dy1*dy1) + A1.w*dx1*dy1;
                    float e0 = __expf(-sg0);
                    float e1 = __expf(-sg1);

                    if (sg0 > 0.0f && sg0 < C0.y) {
                        float alpha = fminf(ALPHA_MAX, B0.y * e0);
                        if (alpha >= ALPHA_MIN) {
                            float w = T * alpha;
                            accr = fmaf(w, B0.z, accr);
                            accg = fmaf(w, B0.w, accg);
                            accb = fmaf(w, C0.x, accb);
                            T *= (1.0f - alpha);
                        }
                    }
                    if (two && sg1 > 0.0f && sg1 < C1.y) {
                        float alpha = fminf(ALPHA_MAX, B1.y * e1);
                        if (alpha >= ALPHA_MIN) {
                            float w = T * alpha;
                            accr = fmaf(w, B1.z, accr);
                            accg = fmaf(w, B1.w, accg);
                            accb = fmaf(w, C1.x, accb);
                            T *= (1.0f - alpha);
                        }
                    }
                }
                if (!__ballot_sync(0xffffffffu, T >= 1e-7f)) { wdone = true; break; }
            }
        }
    }

    const int pix = y * WIDTH + x;
    out[0 * HW + pix] = fmaf(background[0], T, accr);
    out[1 * HW + pix] = fmaf(background[1], T, accg);
    out[2 * HW + pix] = fmaf(background[2], T, accb);
}

// ---------------------------------------------------------------------------
extern "C" void kernel_launch(void* const* d_in, const int* in_sizes, int n_in,
                              void* d_out, int out_size)
{
    const float* means2d    = (const float*)d_in[0];
    const float* conics     = (const float*)d_in[1];
    const float* colors     = (const float*)d_in[2];
    const float* opacities  = (const float*)d_in[3];
    const float* depths     = (const float*)d_in[4];
    const float* background = (const float*)d_in[5];
    float* out = (float*)d_out;

    sort_scatter_kernel<<<128, 256>>>(means2d, conics, colors, opacities, depths);
    dim3 grid(WIDTH / 16, HEIGHT / 16);
    render_kernel<<<grid, 256>>>(background, out);
}

// round 6
// speedup vs baseline: 1.6774x; 1.3361x over previous
#include <cuda_runtime.h>
#include <cuda_bf16.h>
#include <math.h>

#define N_GAUSS 2048
#define HEIGHT  192
#define WIDTH   192
#define HW      (HEIGHT*WIDTH)
#define ALPHA_MAX 0.999f
#define ALPHA_MIN (1.0f/255.0f)
#define NSEG    4
#define SEG     (N_GAUSS / NSEG)   // 512

// Depth-sorted gaussian data
__device__ float4 g_A[N_GAUSS];  // mx, my, conic_a, conic_b
__device__ float4 g_B[N_GAUSS];  // conic_c, opacity, col_r, col_g
__device__ float2 g_C[N_GAUSS];  // col_b, sigma_threshold = log(255*op)+margin
__device__ float2 g_D[N_GAUSS];  // rx, ry : AABB half-extents
// Per-segment partial composites: (accR, accG, accB, T_seg)
__device__ float4 g_seg[NSEG][HW];

// ---------------------------------------------------------------------------
// Kernel 1: rank-by-counting sort (keys unique) fused with param scatter.
// ---------------------------------------------------------------------------
__global__ void __launch_bounds__(256)
sort_scatter_kernel(const float* __restrict__ means2d,
                    const float* __restrict__ conics,
                    const float* __restrict__ colors,
                    const float* __restrict__ opacities,
                    const float* __restrict__ depths)
{
    __shared__ unsigned long long keys[N_GAUSS];
    __shared__ int cnt[16][17];
    const int tid = threadIdx.x;

    #pragma unroll
    for (int i = tid; i < N_GAUSS; i += 256)
        keys[i] = (((unsigned long long)__float_as_uint(depths[i])) << 32) | (unsigned)i;
    __syncthreads();

    const int gl    = tid & 15;
    const int slice = tid >> 4;
    const unsigned long long mykey = keys[blockIdx.x * 16 + gl];

    int c = 0;
    const int s0 = slice * (N_GAUSS / 16);
    #pragma unroll 8
    for (int i = 0; i < N_GAUSS / 16; ++i)
        c += (keys[s0 + i] < mykey);
    cnt[slice][gl] = c;
    __syncthreads();

    if (tid < 16) {
        int rank = 0;
        #pragma unroll
        for (int s = 0; s < 16; ++s) rank += cnt[s][tid];
        int src = blockIdx.x * 16 + tid;
        float mx = means2d[2*src + 0];
        float my = means2d[2*src + 1];
        float ca = conics[3*src + 0];
        float cb = conics[3*src + 1];
        float cc = conics[3*src + 2];
        float op = opacities[src];
        float cr = colors[3*src + 0];
        float cg = colors[3*src + 1];
        float cbl= colors[3*src + 2];
        float t = logf(255.0f * op) + 1e-4f;            // alpha>=1/255 bound
        float det = ca * cc - cb * cb;
        float inv = 2.0f * fmaxf(t, 0.0f) / det;
        float rx = sqrtf(fmaxf(inv * cc, 0.0f)) + 1e-3f;
        float ry = sqrtf(fmaxf(inv * ca, 0.0f)) + 1e-3f;
        g_A[rank] = make_float4(mx, my, ca, cb);
        g_B[rank] = make_float4(cc, op, cr, cg);
        g_C[rank] = make_float2(cbl, t);
        g_D[rank] = make_float2(rx, ry);
    }
}

// ---------------------------------------------------------------------------
// Kernel 2: depth-segmented, per-warp strip-culled compositing.
// grid (12,12,NSEG): block z handles gaussians [z*SEG, (z+1)*SEG) for one
// 16x16 tile; compositing is associative across segments. 576 blocks ->
// ~4 co-resident/SM: latency hiding + load redistribution. Single smem stage.
// ---------------------------------------------------------------------------
__global__ void __launch_bounds__(256)
render_seg_kernel()
{
    __shared__ float4 sA[SEG];
    __shared__ float4 sB[SEG];
    __shared__ float2 sC[SEG];
    __shared__ float2 sD[SEG];

    const int tid  = threadIdx.x;
    const int warp = tid >> 5, lane = tid & 31;
    const int seg  = blockIdx.z;
    const int base = seg * SEG;
    const int x = blockIdx.x * 16 + (tid & 15);
    const int y = blockIdx.y * 16 + (tid >> 4);
    const float px = (float)x + 0.5f;
    const float py = (float)y + 0.5f;

    const float sxmin = blockIdx.x * 16 + 0.5f;
    const float sxmax = blockIdx.x * 16 + 15.5f;
    const float symin = blockIdx.y * 16 + 2 * warp + 0.5f;
    const float symax = symin + 1.0f;

    #pragma unroll
    for (int k = 0; k < SEG / 256; ++k) {
        int i = tid + k * 256;
        sA[i] = g_A[base + i];
        sB[i] = g_B[base + i];
        sC[i] = g_C[base + i];
        sD[i] = g_D[base + i];
    }
    __syncthreads();

    float T = 1.0f;
    float accr = 0.0f, accg = 0.0f, accb = 0.0f;

    for (int g = 0; g < SEG; g += 32) {
        // Lane-parallel cull of this 32-group against the warp's 16x2 strip.
        float4 a = sA[g + lane];
        float2 r = sD[g + lane];
        bool pred = (a.x - r.x <= sxmax) & (a.x + r.x >= sxmin) &
                    (a.y - r.y <= symax) & (a.y + r.y >= symin);
        unsigned mask = __ballot_sync(0xffffffffu, pred);

        // 2-wide in-order walk over survivors (paired loads/sigma/exp = ILP;
        // T-chain stays exactly ordered).
        while (mask) {
            int j0 = g + (__ffs(mask) - 1);
            mask &= mask - 1;
            bool two = (mask != 0);
            int j1 = two ? (g + (__ffs(mask) - 1)) : j0;
            if (two) mask &= mask - 1;

            float4 A0 = sA[j0], A1 = sA[j1];
            float4 B0 = sB[j0], B1 = sB[j1];
            float2 C0 = sC[j0], C1 = sC[j1];

            float dx0 = px - A0.x, dy0 = py - A0.y;
            float dx1 = px - A1.x, dy1 = py - A1.y;
            float sg0 = 0.5f * (A0.z*dx0*dx0 + B0.x*dy0*dy0) + A0.w*dx0*dy0;
            float sg1 = 0.5f * (A1.z*dx1*dx1 + B1.x*dy1*dy1) + A1.w*dx1*dy1;
            float e0 = __expf(-sg0);
            float e1 = __expf(-sg1);

            if (sg0 > 0.0f && sg0 < C0.y) {
                float alpha = fminf(ALPHA_MAX, B0.y * e0);
                if (alpha >= ALPHA_MIN) {           // exact reference condition
                    float w = T * alpha;
                    accr = fmaf(w, B0.z, accr);
                    accg = fmaf(w, B0.w, accg);
                    accb = fmaf(w, C0.x, accb);
                    T *= (1.0f - alpha);
                }
            }
            if (two && sg1 > 0.0f && sg1 < C1.y) {
                float alpha = fminf(ALPHA_MAX, B1.y * e1);
                if (alpha >= ALPHA_MIN) {
                    float w = T * alpha;
                    accr = fmaf(w, B1.z, accr);
                    accg = fmaf(w, B1.w, accg);
                    accb = fmaf(w, C1.x, accb);
                    T *= (1.0f - alpha);
                }
            }
        }
        // Segment-local early exit: remaining in-segment contributions are
        // bounded by T_seg (< 1e-7 absolute after scaling by prefix T <= 1).
        if (!__ballot_sync(0xffffffffu, T >= 1e-7f)) break;
    }

    g_seg[seg][y * WIDTH + x] = make_float4(accr, accg, accb, T);
}

// ---------------------------------------------------------------------------
// Kernel 3: fold segments front-to-back + background.
// ---------------------------------------------------------------------------
__global__ void __launch_bounds__(256)
combine_kernel(const float* __restrict__ background, float* __restrict__ out)
{
    const int pix = blockIdx.x * 256 + threadIdx.x;
    float accr = 0.0f, accg = 0.0f, accb = 0.0f, T = 1.0f;
    #pragma unroll
    for (int s = 0; s < NSEG; ++s) {
        float4 v = g_seg[s][pix];
        accr = fmaf(T, v.x, accr);
        accg = fmaf(T, v.y, accg);
        accb = fmaf(T, v.z, accb);
        T *= v.w;
    }
    out[0 * HW + pix] = fmaf(background[0], T, accr);
    out[1 * HW + pix] = fmaf(background[1], T, accg);
    out[2 * HW + pix] = fmaf(background[2], T, accb);
}

// ---------------------------------------------------------------------------
extern "C" void kernel_launch(void* const* d_in, const int* in_sizes, int n_in,
                              void* d_out, int out_size)
{
    const float* means2d    = (const float*)d_in[0];
    const float* conics     = (const float*)d_in[1];
    const float* colors     = (const float*)d_in[2];
    const float* opacities  = (const float*)d_in[3];
    const float* depths     = (const float*)d_in[4];
    const float* background = (const float*)d_in[5];
    float* out = (float*)d_out;

    sort_scatter_kernel<<<128, 256>>>(means2d, conics, colors, opacities, depths);
    dim3 grid(WIDTH / 16, HEIGHT / 16, NSEG);
    render_seg_kernel<<<grid, 256>>>();
    combine_kernel<<<HW / 256, 256>>>(background, out);
}